// round 1
// baseline (speedup 1.0000x reference)
#include <cuda_runtime.h>
#include <math.h>

#define TS 16
#define CSTEP 4
#define CSTEP2 2

// Scratch: feat1, outs1, feat2, outs2, feat3, outs3, gates (all fp32)
__device__ float g_scratch[47448064];

__device__ __forceinline__ float sigf(float x) { return 1.f / (1.f + __expf(-x)); }

// ---------------------------------------------------------------------------
// Stride-1 3x3 conv (pad 1) for GRU gates (mode 0) and candidate+update (mode 1).
// Input channels: [0,Cx) from xt, [Cx,Cx+Ch) from hprev (mode1: multiplied by r gate).
// block (16,8): each thread -> 2 output rows x 1 col x 8 output channels.
// grid: (B * Cout/8, H/16, W/16)
// ---------------------------------------------------------------------------
__global__ void gru_conv(const float* __restrict__ xt, const float* __restrict__ hprev,
                         const float* __restrict__ Wt, const float* __restrict__ bias,
                         const float* __restrict__ gatesIn, float* __restrict__ out,
                         int Cx, int Ch, int Cout, int H, int W, int mode)
{
    int coutBlocks = Cout >> 3;
    int b   = blockIdx.x / coutBlocks;
    int cb  = blockIdx.x % coutBlocks;
    int co0 = cb * 8;
    int oy0 = blockIdx.y * TS;
    int ox0 = blockIdx.z * TS;
    int tx = threadIdx.x, ty = threadIdx.y;
    int tid = ty * 16 + tx;

    __shared__ float tile[CSTEP][18][19];
    __shared__ float ws[CSTEP][8][9];

    int CinTot = Cx + Ch;
    int CinEff = hprev ? CinTot : Cx;   // h0 == 0 -> skip h channels at t=0

    float acc0[8], acc1[8];
#pragma unroll
    for (int i = 0; i < 8; i++) { acc0[i] = 0.f; acc1[i] = 0.f; }

    for (int ci0 = 0; ci0 < CinEff; ci0 += CSTEP) {
        __syncthreads();
        // load input tile (18x18 per channel, zero-padded borders)
        for (int i = tid; i < CSTEP * 324; i += 128) {
            int c = i / 324, p = i % 324;
            int ly = p / 18, lx = p % 18;
            int gy = oy0 - 1 + ly, gx = ox0 - 1 + lx;
            float v = 0.f;
            if (gy >= 0 && gy < H && gx >= 0 && gx < W) {
                int ci = ci0 + c;
                if (ci < Cx) {
                    v = xt[(((size_t)b * Cx + ci) * H + gy) * W + gx];
                } else {
                    int ch = ci - Cx;
                    v = hprev[(((size_t)b * Ch + ch) * H + gy) * W + gx];
                    if (mode) v *= gatesIn[(((size_t)b * 2 * Ch + ch) * H + gy) * W + gx]; // r*h
                }
            }
            tile[c][ly][lx] = v;
        }
        // load weights for this (cout block, cin step)
        for (int i = tid; i < CSTEP * 72; i += 128) {
            int c = i / 72, r = i % 72;
            int co = r / 9, k = r % 9;
            ws[c][co][k] = Wt[((size_t)(co0 + co) * CinTot + (ci0 + c)) * 9 + k];
        }
        __syncthreads();

#pragma unroll
        for (int c = 0; c < CSTEP; c++) {
            float a[4][3];
#pragma unroll
            for (int i = 0; i < 4; i++)
#pragma unroll
                for (int j = 0; j < 3; j++)
                    a[i][j] = tile[c][2 * ty + i][tx + j];
#pragma unroll
            for (int co = 0; co < 8; co++) {
                float w0 = ws[c][co][0], w1 = ws[c][co][1], w2 = ws[c][co][2];
                float w3 = ws[c][co][3], w4 = ws[c][co][4], w5 = ws[c][co][5];
                float w6 = ws[c][co][6], w7 = ws[c][co][7], w8 = ws[c][co][8];
                acc0[co] += a[0][0]*w0 + a[0][1]*w1 + a[0][2]*w2
                          + a[1][0]*w3 + a[1][1]*w4 + a[1][2]*w5
                          + a[2][0]*w6 + a[2][1]*w7 + a[2][2]*w8;
                acc1[co] += a[1][0]*w0 + a[1][1]*w1 + a[1][2]*w2
                          + a[2][0]*w3 + a[2][1]*w4 + a[2][2]*w5
                          + a[3][0]*w6 + a[3][1]*w7 + a[3][2]*w8;
            }
        }
    }

    int oy = oy0 + 2 * ty, ox = ox0 + tx;
    if (mode == 0) {
#pragma unroll
        for (int co = 0; co < 8; co++) {
            float bz = bias[co0 + co];
            size_t o = (((size_t)b * Cout + co0 + co) * H + oy) * W + ox;
            out[o]     = sigf(acc0[co] + bz);
            out[o + W] = sigf(acc1[co] + bz);
        }
    } else {
#pragma unroll
        for (int co = 0; co < 8; co++) {
            float bz = bias[co0 + co];
            int cc = co0 + co;
            size_t zo = (((size_t)b * 2 * Ch + Ch + cc) * H + oy) * W + ox;
            float z0 = gatesIn[zo], z1 = gatesIn[zo + W];
            float h0v = 0.f, h1v = 0.f;
            if (hprev) {
                size_t ho = (((size_t)b * Ch + cc) * H + oy) * W + ox;
                h0v = hprev[ho]; h1v = hprev[ho + W];
            }
            size_t o = (((size_t)b * Ch + cc) * H + oy) * W + ox;
            out[o]     = z0 * h0v + (1.f - z0) * tanhf(acc0[co] + bz);
            out[o + W] = z1 * h1v + (1.f - z1) * tanhf(acc1[co] + bz);
        }
    }
}

// ---------------------------------------------------------------------------
// Stride-2 3x3 conv (pad 1) + leaky relu(0.2), over all N = T*B samples.
// Input sample n=(t,b) at in + t*sOuter + b*sInner. Output (T,B,Cout,Hout,Wout).
// block (16,8): each thread -> 2 output rows x 1 col x 8 output channels.
// grid: (N * Cout/8, Hout/16, Wout/16)
// ---------------------------------------------------------------------------
__global__ void conv_s2_lrelu(const float* __restrict__ in, const float* __restrict__ Wt,
                              const float* __restrict__ bias, float* __restrict__ out,
                              int Cin, int Cout, int Hin, int Win, int sOuter, int sInner)
{
    int coutBlocks = Cout >> 3;
    int n  = blockIdx.x / coutBlocks;
    int cb = blockIdx.x % coutBlocks;
    int co0 = cb * 8;
    int t = n / 8, b = n % 8;
    const float* inN = in + (size_t)t * sOuter + (size_t)b * sInner;
    int Hout = Hin >> 1, Wout = Win >> 1;
    int oy0 = blockIdx.y * TS, ox0 = blockIdx.z * TS;
    int tx = threadIdx.x, ty = threadIdx.y;
    int tid = ty * 16 + tx;

    __shared__ float tile[CSTEP2][33][35];
    __shared__ float ws[CSTEP2][8][9];

    float acc0[8], acc1[8];
#pragma unroll
    for (int i = 0; i < 8; i++) { acc0[i] = 0.f; acc1[i] = 0.f; }

    for (int ci0 = 0; ci0 < Cin; ci0 += CSTEP2) {
        __syncthreads();
        for (int i = tid; i < CSTEP2 * 1089; i += 128) {
            int c = i / 1089, p = i % 1089;
            int ly = p / 33, lx = p % 33;
            int gy = 2 * oy0 - 1 + ly, gx = 2 * ox0 - 1 + lx;
            float v = 0.f;
            int ci = ci0 + c;
            if (ci < Cin && gy >= 0 && gy < Hin && gx >= 0 && gx < Win)
                v = inN[((size_t)ci * Hin + gy) * Win + gx];
            tile[c][ly][lx] = v;
        }
        for (int i = tid; i < CSTEP2 * 72; i += 128) {
            int c = i / 72, r = i % 72;
            int co = r / 9, k = r % 9;
            float wv = 0.f;
            if (ci0 + c < Cin)
                wv = Wt[((size_t)(co0 + co) * Cin + (ci0 + c)) * 9 + k];
            ws[c][co][k] = wv;
        }
        __syncthreads();

#pragma unroll
        for (int c = 0; c < CSTEP2; c++) {
            float a[5][3];
#pragma unroll
            for (int i = 0; i < 5; i++)
#pragma unroll
                for (int j = 0; j < 3; j++)
                    a[i][j] = tile[c][4 * ty + i][2 * tx + j];
#pragma unroll
            for (int co = 0; co < 8; co++) {
                float w0 = ws[c][co][0], w1 = ws[c][co][1], w2 = ws[c][co][2];
                float w3 = ws[c][co][3], w4 = ws[c][co][4], w5 = ws[c][co][5];
                float w6 = ws[c][co][6], w7 = ws[c][co][7], w8 = ws[c][co][8];
                acc0[co] += a[0][0]*w0 + a[0][1]*w1 + a[0][2]*w2
                          + a[1][0]*w3 + a[1][1]*w4 + a[1][2]*w5
                          + a[2][0]*w6 + a[2][1]*w7 + a[2][2]*w8;
                acc1[co] += a[2][0]*w0 + a[2][1]*w1 + a[2][2]*w2
                          + a[3][0]*w3 + a[3][1]*w4 + a[3][2]*w5
                          + a[4][0]*w6 + a[4][1]*w7 + a[4][2]*w8;
            }
        }
    }

    int oy = oy0 + 2 * ty, ox = ox0 + tx;
#pragma unroll
    for (int co = 0; co < 8; co++) {
        float bz = bias[co0 + co];
        float v0 = acc0[co] + bz, v1 = acc1[co] + bz;
        v0 = v0 > 0.f ? v0 : 0.2f * v0;
        v1 = v1 > 0.f ? v1 : 0.2f * v1;
        size_t o = (((size_t)n * Cout + co0 + co) * Hout + oy) * Wout + ox;
        out[o]        = v0;
        out[o + Wout] = v1;
    }
}

extern "C" void kernel_launch(void* const* d_in, const int* in_sizes, int n_in,
                              void* d_out, int out_size)
{
    const float* x   = (const float*)d_in[0];
    const float* W1  = (const float*)d_in[1];
    const float* b1  = (const float*)d_in[2];
    const float* Wg1 = (const float*)d_in[3];
    const float* bg1 = (const float*)d_in[4];
    const float* Wc1 = (const float*)d_in[5];
    const float* bc1 = (const float*)d_in[6];
    const float* W2  = (const float*)d_in[7];
    const float* b2  = (const float*)d_in[8];
    const float* Wg2 = (const float*)d_in[9];
    const float* bg2 = (const float*)d_in[10];
    const float* Wc2 = (const float*)d_in[11];
    const float* bc2 = (const float*)d_in[12];
    const float* W3  = (const float*)d_in[13];
    const float* b3  = (const float*)d_in[14];
    const float* Wg3 = (const float*)d_in[15];
    const float* bg3 = (const float*)d_in[16];
    const float* Wc3 = (const float*)d_in[17];
    const float* bc3 = (const float*)d_in[18];

    float* base = nullptr;
    cudaGetSymbolAddress((void**)&base, g_scratch);

    float* feat1 = base;                 // 10*8*16*64*64  = 5242880
    float* outs1 = base + 5242880;       // 10*8*64*64*64  = 20971520
    float* feat2 = base + 26214400;      // 10*8*64*32*32  = 5242880
    float* outs2 = base + 31457280;      // 10*8*96*32*32  = 7864320
    float* feat3 = base + 39321600;      // 10*8*96*16*16  = 1966080
    float* outs3 = base + 41287680;      // 10*8*96*16*16  = 1966080
    float* gates = base + 43253760;      // max 8*128*64*64 = 4194304

    dim3 blk(16, 8);

    // ---------------- Stage 1 ----------------
    // feat1 = lrelu(conv_s2(x)) : x is (B=8,T=10,1,128,128) -> map (t,b)
    conv_s2_lrelu<<<dim3(80 * 2, 4, 4), blk>>>(x, W1, b1, feat1,
                                               1, 16, 128, 128, 16384, 163840);
    for (int t = 0; t < 10; t++) {
        const float* xt = feat1 + (size_t)t * 8 * 16 * 64 * 64;
        const float* hp = t ? outs1 + (size_t)(t - 1) * 8 * 64 * 64 * 64 : nullptr;
        float* hn = outs1 + (size_t)t * 8 * 64 * 64 * 64;
        gru_conv<<<dim3(8 * 16, 4, 4), blk>>>(xt, hp, Wg1, bg1, gates, gates,
                                              16, 64, 128, 64, 64, 0);
        gru_conv<<<dim3(8 * 8, 4, 4), blk>>>(xt, hp, Wc1, bc1, gates, hn,
                                             16, 64, 64, 64, 64, 1);
    }

    // ---------------- Stage 2 ----------------
    conv_s2_lrelu<<<dim3(80 * 8, 2, 2), blk>>>(outs1, W2, b2, feat2,
                                               64, 64, 64, 64, 8 * 64 * 4096, 64 * 4096);
    for (int t = 0; t < 10; t++) {
        const float* xt = feat2 + (size_t)t * 8 * 64 * 32 * 32;
        const float* hp = t ? outs2 + (size_t)(t - 1) * 8 * 96 * 32 * 32 : nullptr;
        float* hn = outs2 + (size_t)t * 8 * 96 * 32 * 32;
        gru_conv<<<dim3(8 * 24, 2, 2), blk>>>(xt, hp, Wg2, bg2, gates, gates,
                                              64, 96, 192, 32, 32, 0);
        gru_conv<<<dim3(8 * 12, 2, 2), blk>>>(xt, hp, Wc2, bc2, gates, hn,
                                              64, 96, 96, 32, 32, 1);
    }

    // ---------------- Stage 3 ----------------
    conv_s2_lrelu<<<dim3(80 * 12, 1, 1), blk>>>(outs2, W3, b3, feat3,
                                                96, 96, 32, 32, 8 * 96 * 1024, 96 * 1024);
    for (int t = 0; t < 10; t++) {
        const float* xt = feat3 + (size_t)t * 8 * 96 * 16 * 16;
        const float* hp = t ? outs3 + (size_t)(t - 1) * 8 * 96 * 16 * 16 : nullptr;
        float* hn = outs3 + (size_t)t * 8 * 96 * 16 * 16;
        gru_conv<<<dim3(8 * 24, 1, 1), blk>>>(xt, hp, Wg3, bg3, gates, gates,
                                              96, 96, 192, 16, 16, 0);
        gru_conv<<<dim3(8 * 12, 1, 1), blk>>>(xt, hp, Wc3, bc3, gates, hn,
                                              96, 96, 96, 16, 16, 1);
    }

    // ---------------- Assemble output: (h1, h2, h3) flattened ----------------
    float* out = (float*)d_out;
    cudaMemcpyAsync(out,
                    outs1 + 9UL * 8 * 64 * 4096,
                    (size_t)8 * 64 * 4096 * sizeof(float),
                    cudaMemcpyDeviceToDevice, 0);
    cudaMemcpyAsync(out + 2097152,
                    outs2 + 9UL * 8 * 96 * 1024,
                    (size_t)8 * 96 * 1024 * sizeof(float),
                    cudaMemcpyDeviceToDevice, 0);
    cudaMemcpyAsync(out + 2097152 + 786432,
                    outs3 + 9UL * 8 * 96 * 256,
                    (size_t)8 * 96 * 256 * sizeof(float),
                    cudaMemcpyDeviceToDevice, 0);
}